// round 15
// baseline (speedup 1.0000x reference)
#include <cuda_runtime.h>
#include <cuda_bf16.h>

#define B_   16
#define C_   256
#define S_   1024
#define H_   4
#define O3_  768
#define SCALE_ 0.125f
#define LOG2E_ 1.4426950408889634f

__device__ __align__(16) __nv_bfloat16 g_qkvh[B_ * S_ * O3_];  // [b][s][768]
__device__ __align__(16) __nv_bfloat16 g_xh  [B_ * C_ * S_];   // [b][c][s]
__device__ __align__(16) __nv_bfloat16 g_wph [C_ * O3_];
__device__ __align__(16) __nv_bfloat16 g_woh [C_ * C_];

// ---------------------------------------------------------------------------
__device__ __forceinline__ unsigned smem_u32(const void* p) {
    return (unsigned)__cvta_generic_to_shared(p);
}
__device__ __forceinline__ void ldsm4(unsigned& r0, unsigned& r1, unsigned& r2, unsigned& r3,
                                      unsigned a) {
    asm volatile("ldmatrix.sync.aligned.m8n8.x4.shared.b16 {%0,%1,%2,%3},[%4];"
                 : "=r"(r0), "=r"(r1), "=r"(r2), "=r"(r3) : "r"(a));
}
__device__ __forceinline__ void ldsm4t(unsigned& r0, unsigned& r1, unsigned& r2, unsigned& r3,
                                       unsigned a) {
    asm volatile("ldmatrix.sync.aligned.m8n8.x4.trans.shared.b16 {%0,%1,%2,%3},[%4];"
                 : "=r"(r0), "=r"(r1), "=r"(r2), "=r"(r3) : "r"(a));
}
__device__ __forceinline__ void mma16(float c[4], const unsigned a[4], const unsigned b[2]) {
    asm volatile("mma.sync.aligned.m16n8k16.row.col.f32.bf16.bf16.f32 "
                 "{%0,%1,%2,%3},{%4,%5,%6,%7},{%8,%9},{%0,%1,%2,%3};"
                 : "+f"(c[0]), "+f"(c[1]), "+f"(c[2]), "+f"(c[3])
                 : "r"(a[0]), "r"(a[1]), "r"(a[2]), "r"(a[3]),
                   "r"(b[0]), "r"(b[1]));
}
#define CP16(dst, src) \
    asm volatile("cp.async.cg.shared.global [%0], [%1], 16;" :: "r"(dst), "l"(src))
#define CPCOMMIT() asm volatile("cp.async.commit_group;")
#define CPWAIT(n)  asm volatile("cp.async.wait_group %0;" :: "n"(n))

__device__ __forceinline__ unsigned packbf(float lo, float hi) {
    __nv_bfloat162 v = __floats2bfloat162_rn(lo, hi);
    return *(unsigned*)&v;
}
__device__ __forceinline__ float exp2fast(float x) {
    x = fmaxf(x, -126.0f);
    float z = x + 12582912.0f;
    int   n = __float_as_int(z) - 0x4B400000;
    float f = x - (z - 12582912.0f);
    float p = 0.0013333558f;
    p = fmaf(p, f, 0.0096181291f);
    p = fmaf(p, f, 0.0555041087f);
    p = fmaf(p, f, 0.2402265070f);
    p = fmaf(p, f, 0.6931471806f);
    p = fmaf(p, f, 1.0f);
    return __int_as_float(__float_as_int(p) + (n << 23));
}

// ---------------------------------------------------------------------------
// Kernel 0: convert inputs to bf16.
// ---------------------------------------------------------------------------
#define NX4  (B_ * C_ * S_ / 4)
#define NWP4 (C_ * O3_ / 4)
#define NWO4 (C_ * C_ / 4)
__global__ void __launch_bounds__(256) cvt_inputs(const float* __restrict__ x,
                                                  const float* __restrict__ wp,
                                                  const float* __restrict__ wo) {
    int idx = blockIdx.x * 256 + threadIdx.x;
    const int total = NX4 + NWP4 + NWO4;
    if (idx >= total) return;
    const float* src; __nv_bfloat16* dst; int i;
    if (idx < NX4)              { src = x;  dst = g_xh;  i = idx; }
    else if (idx < NX4 + NWP4)  { src = wp; dst = g_wph; i = idx - NX4; }
    else                        { src = wo; dst = g_woh; i = idx - NX4 - NWP4; }
    float4 v = *(const float4*)&src[i * 4];
    *(__nv_bfloat162*)&dst[i * 4]     = __floats2bfloat162_rn(v.x, v.y);
    *(__nv_bfloat162*)&dst[i * 4 + 2] = __floats2bfloat162_rn(v.z, v.w);
}

// ---------------------------------------------------------------------------
// Kernel 1: QKV projection. CTA 128x128, 8 warps, k-chunks 64, 3-stage ring.
// (identical to the 115.2us round-13 build)
// ---------------------------------------------------------------------------
#define Q_ST 17408u
#define Q_SM (6u * Q_ST)
__global__ void __launch_bounds__(256, 2) qkv3(const float* __restrict__ bp) {
    extern __shared__ __align__(16) char dsm[];
    const unsigned sa = smem_u32(dsm), sbb = sa + 3 * Q_ST;
    const int b  = blockIdx.z;
    const int m0 = blockIdx.y * 128;
    const int n0 = blockIdx.x * 128;
    const int tid = threadIdx.x, warp = tid >> 5, lane = tid & 31;
    const int g = lane >> 2, t = lane & 3;
    const int l7 = lane & 7, lq1 = (lane >> 3) & 1, lq2 = (lane >> 4) & 1;
    const int wm = (warp >> 1) * 32, wn = (warp & 1) * 64;
    const __nv_bfloat16* xb = g_xh + (size_t)b * C_ * S_;

    const int lk = tid >> 4, lc = (tid & 15) * 8;

#pragma unroll
    for (int p = 0; p < 4; p++) {
        int kk = lk + p * 16;
        CP16(sa  + (kk * 136 + lc) * 2, xb + (size_t)kk * S_ + m0 + lc);
        CP16(sbb + (kk * 136 + lc) * 2, g_wph + (size_t)kk * O3_ + n0 + lc);
    }
    CPCOMMIT();

    float acc[2][8][4];
#pragma unroll
    for (int mt = 0; mt < 2; mt++)
#pragma unroll
        for (int nt = 0; nt < 8; nt++)
#pragma unroll
            for (int i = 0; i < 4; i++) acc[mt][nt][i] = 0.f;

#pragma unroll
    for (int it = 0; it < 4; it++) {
        if (it + 1 < 4) {
            const int k0 = (it + 1) * 64;
            const unsigned ao = sa  + ((it + 1) % 3) * Q_ST;
            const unsigned bo = sbb + ((it + 1) % 3) * Q_ST;
#pragma unroll
            for (int p = 0; p < 4; p++) {
                int kk = lk + p * 16;
                CP16(ao + (kk * 136 + lc) * 2, xb + (size_t)(k0 + kk) * S_ + m0 + lc);
                CP16(bo + (kk * 136 + lc) * 2, g_wph + (size_t)(k0 + kk) * O3_ + n0 + lc);
            }
            CPCOMMIT();
            CPWAIT(1);
        } else {
            CPWAIT(0);
        }
        __syncthreads();
        const unsigned ao = sa  + (it % 3) * Q_ST;
        const unsigned bo = sbb + (it % 3) * Q_ST;
#pragma unroll
        for (int ks = 0; ks < 4; ks++) {
            const int kb = ks * 16;
            unsigned a[2][4];
#pragma unroll
            for (int mt = 0; mt < 2; mt++)
                ldsm4t(a[mt][0], a[mt][1], a[mt][2], a[mt][3],
                       ao + ((kb + lq2 * 8 + l7) * 136 + wm + mt * 16 + lq1 * 8) * 2);
#pragma unroll
            for (int np = 0; np < 4; np++) {
                unsigned r0, r1, r2, r3;
                ldsm4t(r0, r1, r2, r3,
                       bo + ((kb + lq1 * 8 + l7) * 136 + wn + np * 16 + lq2 * 8) * 2);
                unsigned blo[2] = {r0, r1}, bhi[2] = {r2, r3};
#pragma unroll
                for (int mt = 0; mt < 2; mt++) {
                    mma16(acc[mt][2 * np],     a[mt], blo);
                    mma16(acc[mt][2 * np + 1], a[mt], bhi);
                }
            }
        }
    }

    __syncthreads();
    __nv_bfloat16* Ts = (__nv_bfloat16*)dsm;
#pragma unroll
    for (int mt = 0; mt < 2; mt++) {
        const int r1 = wm + mt * 16 + g, r2 = r1 + 8;
#pragma unroll
        for (int nt = 0; nt < 8; nt++) {
            const int cn = wn + nt * 8 + 2 * t;
            float2 bb = *(const float2*)&bp[n0 + cn];
            *(unsigned*)&Ts[r1 * 136 + cn] = packbf(acc[mt][nt][0] + bb.x, acc[mt][nt][1] + bb.y);
            *(unsigned*)&Ts[r2 * 136 + cn] = packbf(acc[mt][nt][2] + bb.x, acc[mt][nt][3] + bb.y);
        }
    }
    __syncthreads();
    __nv_bfloat16* qb = g_qkvh + (size_t)b * S_ * O3_;
#pragma unroll
    for (int i = 0; i < 8; i++) {
        int idx = tid + i * 256;
        int row = idx >> 4, c16 = (idx & 15) * 8;
        uint4 v = *(uint4*)&Ts[row * 136 + c16];
        *(uint4*)&qb[(size_t)(m0 + row) * O3_ + n0 + c16] = v;
    }
}

// ---------------------------------------------------------------------------
// Kernel 2: FUSED attention + out-projection.
// CTA = (128 s-rows, batch). 256 threads / 8 warps.
// Phase A: 4 heads sequentially, flash attention (no-max softmax), output
//          written to smem Ao[128][264] bf16.
// Phase B: out GEMM from Ao (LDSM) x w_out (3-stage cp.async ring), two
//          n=128 halves; bias + residual + transposed fp32 store.
// smem: Ao 67584B | region2 67584B (KV ring 55296 / B ring 52224 / Os 67584)
// ---------------------------------------------------------------------------
#define KVS   9216u
#define AO_W  264
#define AO_SZ 67584u
#define FB_ST 17408u
#define F_SM  (AO_SZ + 67584u)   // 135168
__global__ void __launch_bounds__(256, 1) attn_out(const float* __restrict__ bo,
                                                   const float* __restrict__ x,
                                                   float* __restrict__ out) {
    extern __shared__ __align__(16) char dsm[];
    const unsigned aob = smem_u32(dsm);
    const unsigned r2  = aob + AO_SZ;
    const int m0 = blockIdx.x * 128;
    const int b  = blockIdx.y;
    const __nv_bfloat16* qkv = g_qkvh + (size_t)b * S_ * O3_;

    const int tid = threadIdx.x, warp = tid >> 5, lane = tid & 31;
    const int g = lane >> 2, t = lane & 3;
    const int l7 = lane & 7, lq1 = (lane >> 3) & 1, lq2 = (lane >> 4) & 1;
    const unsigned ks_b = r2, vs_b = r2 + 3 * KVS;
    const float k2 = SCALE_ * LOG2E_;
    const int lj = tid >> 2, lc8 = (tid & 3) * 16;
    __nv_bfloat16* Ao = (__nv_bfloat16*)dsm;

    // ---------------- Phase A: attention, 4 heads sequentially ----------------
    for (int h = 0; h < H_; h++) {
        __syncthreads();   // ring stages from previous head fully consumed

        unsigned qa[4][4];
        {
            const __nv_bfloat16* q1 = qkv + (size_t)(m0 + warp * 16 + g) * O3_ + h * 192;
            const __nv_bfloat16* q2 = q1 + 8 * O3_;
#pragma unroll
            for (int c = 0; c < 4; c++) {
                qa[c][0] = *(const unsigned*)&q1[c * 16 + 2 * t];
                qa[c][1] = *(const unsigned*)&q2[c * 16 + 2 * t];
                qa[c][2] = *(const unsigned*)&q1[c * 16 + 8 + 2 * t];
                qa[c][3] = *(const unsigned*)&q2[c * 16 + 8 + 2 * t];
            }
        }

        float oacc[8][4];
#pragma unroll
        for (int nt = 0; nt < 8; nt++)
#pragma unroll
            for (int i = 0; i < 4; i++) oacc[nt][i] = 0.f;
        float l1 = 0.f, l2 = 0.f;

        {   // tile 0 -> stage 0
            const __nv_bfloat16* src = qkv + (size_t)lj * O3_ + h * 192 + 64 + lc8;
            CP16(ks_b + (lj * 72 + lc8) * 2,     src);
            CP16(ks_b + (lj * 72 + lc8 + 8) * 2, src + 8);
            CP16(vs_b + (lj * 72 + lc8) * 2,     src + 64);
            CP16(vs_b + (lj * 72 + lc8 + 8) * 2, src + 72);
            CPCOMMIT();
        }

        for (int jt = 0; jt < 16; jt++) {
            if (jt + 1 < 16) {
                const unsigned ko = ks_b + ((jt + 1) % 3) * KVS;
                const unsigned vo = vs_b + ((jt + 1) % 3) * KVS;
                const __nv_bfloat16* src = qkv + (size_t)((jt + 1) * 64 + lj) * O3_ + h * 192 + 64 + lc8;
                CP16(ko + (lj * 72 + lc8) * 2,     src);
                CP16(ko + (lj * 72 + lc8 + 8) * 2, src + 8);
                CP16(vo + (lj * 72 + lc8) * 2,     src + 64);
                CP16(vo + (lj * 72 + lc8 + 8) * 2, src + 72);
                CPCOMMIT();
                CPWAIT(1);
            } else {
                CPWAIT(0);
            }
            __syncthreads();
            const unsigned ko = ks_b + (jt % 3) * KVS;
            const unsigned vo = vs_b + (jt % 3) * KVS;

            float sacc[8][4];
#pragma unroll
            for (int nt = 0; nt < 8; nt++)
#pragma unroll
                for (int i = 0; i < 4; i++) sacc[nt][i] = 0.f;
#pragma unroll
            for (int c = 0; c < 4; c++) {
                const int kb = c * 16;
#pragma unroll
                for (int np = 0; np < 4; np++) {
                    unsigned r0, r1, r2v, r3;
                    ldsm4(r0, r1, r2v, r3,
                          ko + ((np * 16 + lq2 * 8 + l7) * 72 + kb + lq1 * 8) * 2);
                    unsigned blo[2] = {r0, r1}, bhi[2] = {r2v, r3};
                    mma16(sacc[2 * np],     qa[c], blo);
                    mma16(sacc[2 * np + 1], qa[c], bhi);
                }
            }

            unsigned pa[4][4];
#pragma unroll
            for (int jc = 0; jc < 4; jc++) {
                float p0 = exp2fast(sacc[2 * jc][0] * k2);
                float p1 = exp2fast(sacc[2 * jc][1] * k2);
                float p2 = exp2fast(sacc[2 * jc][2] * k2);
                float p3 = exp2fast(sacc[2 * jc][3] * k2);
                float p4 = exp2fast(sacc[2 * jc + 1][0] * k2);
                float p5 = exp2fast(sacc[2 * jc + 1][1] * k2);
                float p6 = exp2fast(sacc[2 * jc + 1][2] * k2);
                float p7 = exp2fast(sacc[2 * jc + 1][3] * k2);
                l1 += (p0 + p1) + (p4 + p5);
                l2 += (p2 + p3) + (p6 + p7);
                pa[jc][0] = packbf(p0, p1);
                pa[jc][1] = packbf(p2, p3);
                pa[jc][2] = packbf(p4, p5);
                pa[jc][3] = packbf(p6, p7);
            }

#pragma unroll
            for (int jc = 0; jc < 4; jc++) {
                const int kc = jc * 16;
#pragma unroll
                for (int dp = 0; dp < 4; dp++) {
                    unsigned r0, r1, r2v, r3;
                    ldsm4t(r0, r1, r2v, r3,
                           vo + ((kc + lq1 * 8 + l7) * 72 + dp * 16 + lq2 * 8) * 2);
                    unsigned blo[2] = {r0, r1}, bhi[2] = {r2v, r3};
                    mma16(oacc[2 * dp],     pa[jc], blo);
                    mma16(oacc[2 * dp + 1], pa[jc], bhi);
                }
            }
        }

        l1 += __shfl_xor_sync(0xffffffffu, l1, 1);
        l1 += __shfl_xor_sync(0xffffffffu, l1, 2);
        l2 += __shfl_xor_sync(0xffffffffu, l2, 1);
        l2 += __shfl_xor_sync(0xffffffffu, l2, 2);
        const float inv1 = 1.f / l1, inv2 = 1.f / l2;

        // write normalized head output to smem Ao (columns h*64..h*64+63)
        const int r1 = warp * 16 + g, r2r = r1 + 8;
#pragma unroll
        for (int nt = 0; nt < 8; nt++) {
            const int cn = h * 64 + nt * 8 + 2 * t;
            *(unsigned*)&Ao[r1 * AO_W + cn] = packbf(oacc[nt][0] * inv1, oacc[nt][1] * inv1);
            *(unsigned*)&Ao[r2r * AO_W + cn] = packbf(oacc[nt][2] * inv2, oacc[nt][3] * inv2);
        }
    }
    __syncthreads();   // Ao complete

    // ---------------- Phase B: out GEMM + bias + residual + transpose ----------
    const int wm = (warp >> 1) * 32, wn = (warp & 1) * 64;
    const int bk = tid >> 4, bc = (tid & 15) * 8;
    const float* xb = x + (size_t)b * C_ * S_;
    float* ob = out + (size_t)b * C_ * S_;

    for (int nh = 0; nh < 2; nh++) {
        const int n0 = nh * 128;
        __syncthreads();   // Os reads from previous half done before ring overwrite

        // prologue: chunk 0
#pragma unroll
        for (int p = 0; p < 4; p++) {
            int kk = bk + p * 16;
            CP16(r2 + (kk * 136 + bc) * 2, g_woh + (size_t)kk * C_ + n0 + bc);
        }
        CPCOMMIT();

        float acc[2][8][4];
#pragma unroll
        for (int mt = 0; mt < 2; mt++)
#pragma unroll
            for (int nt = 0; nt < 8; nt++)
#pragma unroll
                for (int i = 0; i < 4; i++) acc[mt][nt][i] = 0.f;

#pragma unroll
        for (int it = 0; it < 4; it++) {
            if (it + 1 < 4) {
                const int k0 = (it + 1) * 64;
                const unsigned bo2 = r2 + ((it + 1) % 3) * FB_ST;
#pragma unroll
                for (int p = 0; p < 4; p++) {
                    int kk = bk + p * 16;
                    CP16(bo2 + (kk * 136 + bc) * 2, g_woh + (size_t)(k0 + kk) * C_ + n0 + bc);
                }
                CPCOMMIT();
                CPWAIT(1);
            } else {
                CPWAIT(0);
            }
            __syncthreads();
            const unsigned bo2 = r2 + (it % 3) * FB_ST;
#pragma unroll
            for (int ks = 0; ks < 4; ks++) {
                const int kb = it * 64 + ks * 16;
                unsigned a[2][4];
#pragma unroll
                for (int mt = 0; mt < 2; mt++)
                    ldsm4(a[mt][0], a[mt][1], a[mt][2], a[mt][3],
                          aob + ((wm + mt * 16 + lq1 * 8 + l7) * AO_W + kb + lq2 * 8) * 2);
#pragma unroll
                for (int np = 0; np < 4; np++) {
                    unsigned r0, r1, r2v, r3;
                    ldsm4t(r0, r1, r2v, r3,
                           bo2 + (((ks * 16) + lq1 * 8 + l7) * 136 + wn + np * 16 + lq2 * 8) * 2);
                    unsigned blo[2] = {r0, r1}, bhi[2] = {r2v, r3};
#pragma unroll
                    for (int mt = 0; mt < 2; mt++) {
                        mma16(acc[mt][2 * np],     a[mt], blo);
                        mma16(acc[mt][2 * np + 1], a[mt], bhi);
                    }
                }
            }
        }

        // epilogue: fp32 bounce in region2 (ring dead), coalesced store
        __syncthreads();
        float* Os = (float*)(dsm + AO_SZ);
#pragma unroll
        for (int mt = 0; mt < 2; mt++) {
            const int r1 = wm + mt * 16 + g, r2r = r1 + 8;
#pragma unroll
            for (int nt = 0; nt < 8; nt++) {
                const int cn = wn + nt * 8 + 2 * t;
                Os[cn * 132 + r1]       = acc[mt][nt][0];
                Os[(cn + 1) * 132 + r1] = acc[mt][nt][1];
                Os[cn * 132 + r2r]      = acc[mt][nt][2];
                Os[(cn + 1) * 132 + r2r] = acc[mt][nt][3];
            }
        }
        __syncthreads();
#pragma unroll
        for (int i = 0; i < 16; i++) {
            int idx = tid + i * 256;
            int row = idx >> 5, c4 = (idx & 31) * 4;
            const int ch = n0 + row;
            const float bias = bo[ch];
            float4 v = *(float4*)&Os[row * 132 + c4];
            float4 xr = *(const float4*)&xb[(size_t)ch * S_ + m0 + c4];
            v.x += bias + xr.x; v.y += bias + xr.y;
            v.z += bias + xr.z; v.w += bias + xr.w;
            *(float4*)&ob[(size_t)ch * S_ + m0 + c4] = v;
        }
    }
}

// ---------------------------------------------------------------------------
extern "C" void kernel_launch(void* const* d_in, const int* in_sizes, int n_in,
                              void* d_out, int out_size) {
    const float* x  = (const float*)d_in[0];
    const float* wp = (const float*)d_in[1];
    const float* bp = (const float*)d_in[2];
    const float* wo = (const float*)d_in[3];
    const float* bo = (const float*)d_in[4];
    float* out = (float*)d_out;

    static int attr_set = 0;
    if (!attr_set) {
        cudaFuncSetAttribute(qkv3, cudaFuncAttributeMaxDynamicSharedMemorySize, (int)Q_SM);
        cudaFuncSetAttribute(attn_out, cudaFuncAttributeMaxDynamicSharedMemorySize, (int)F_SM);
        attr_set = 1;
    }

    const int total4 = NX4 + NWP4 + NWO4;
    cvt_inputs<<<(total4 + 255) / 256, 256>>>(x, wp, wo);
    qkv3<<<dim3(O3_ / 128, S_ / 128, B_), 256, Q_SM>>>(bp);
    attn_out<<<dim3(S_ / 128, B_), 256, F_SM>>>(bo, x, out);
}

// round 16
// speedup vs baseline: 1.0709x; 1.0709x over previous
#include <cuda_runtime.h>
#include <cuda_bf16.h>

#define B_   16
#define C_   256
#define S_   1024
#define H_   4
#define O3_  768
#define SCALE_ 0.125f
#define LOG2E_ 1.4426950408889634f

__device__ __align__(16) __nv_bfloat16 g_qkvh[B_ * S_ * O3_];  // [b][s][768]
__device__ __align__(16) __nv_bfloat16 g_aoh [B_ * S_ * C_];   // [b][s][256]
__device__ __align__(16) __nv_bfloat16 g_xh  [B_ * C_ * S_];   // [b][c][s]
__device__ __align__(16) __nv_bfloat16 g_wph [C_ * O3_];
__device__ __align__(16) __nv_bfloat16 g_woh [C_ * C_];

// ---------------------------------------------------------------------------
__device__ __forceinline__ unsigned smem_u32(const void* p) {
    return (unsigned)__cvta_generic_to_shared(p);
}
__device__ __forceinline__ void ldsm4(unsigned& r0, unsigned& r1, unsigned& r2, unsigned& r3,
                                      unsigned a) {
    asm volatile("ldmatrix.sync.aligned.m8n8.x4.shared.b16 {%0,%1,%2,%3},[%4];"
                 : "=r"(r0), "=r"(r1), "=r"(r2), "=r"(r3) : "r"(a));
}
__device__ __forceinline__ void ldsm4t(unsigned& r0, unsigned& r1, unsigned& r2, unsigned& r3,
                                       unsigned a) {
    asm volatile("ldmatrix.sync.aligned.m8n8.x4.trans.shared.b16 {%0,%1,%2,%3},[%4];"
                 : "=r"(r0), "=r"(r1), "=r"(r2), "=r"(r3) : "r"(a));
}
__device__ __forceinline__ void mma16(float c[4], const unsigned a[4], const unsigned b[2]) {
    asm volatile("mma.sync.aligned.m16n8k16.row.col.f32.bf16.bf16.f32 "
                 "{%0,%1,%2,%3},{%4,%5,%6,%7},{%8,%9},{%0,%1,%2,%3};"
                 : "+f"(c[0]), "+f"(c[1]), "+f"(c[2]), "+f"(c[3])
                 : "r"(a[0]), "r"(a[1]), "r"(a[2]), "r"(a[3]),
                   "r"(b[0]), "r"(b[1]));
}
#define CP16(dst, src) \
    asm volatile("cp.async.cg.shared.global [%0], [%1], 16;" :: "r"(dst), "l"(src))
#define CPCOMMIT() asm volatile("cp.async.commit_group;")
#define CPWAIT(n)  asm volatile("cp.async.wait_group %0;" :: "n"(n))

__device__ __forceinline__ unsigned packbf(float lo, float hi) {
    __nv_bfloat162 v = __floats2bfloat162_rn(lo, hi);
    return *(unsigned*)&v;
}
__device__ __forceinline__ float exp2fast(float x) {
    x = fmaxf(x, -126.0f);
    float z = x + 12582912.0f;
    int   n = __float_as_int(z) - 0x4B400000;
    float f = x - (z - 12582912.0f);
    float p = 0.0013333558f;
    p = fmaf(p, f, 0.0096181291f);
    p = fmaf(p, f, 0.0555041087f);
    p = fmaf(p, f, 0.2402265070f);
    p = fmaf(p, f, 0.6931471806f);
    p = fmaf(p, f, 1.0f);
    return __int_as_float(__float_as_int(p) + (n << 23));
}

// ---------------------------------------------------------------------------
// Kernel 0: convert inputs to bf16. High-MLP version: each thread processes
// 4 independent float4 chunks per iteration (loads batched before stores).
// ---------------------------------------------------------------------------
#define NX4  (B_ * C_ * S_ / 4)       // 1048576
#define NWP4 (C_ * O3_ / 4)           // 49152
#define NWO4 (C_ * C_ / 4)            // 16384
#define CVT_TOT   (NX4 + NWP4 + NWO4) // 1114112
#define CVT_GRID  1184
__global__ void __launch_bounds__(256) cvt_inputs(const float* __restrict__ x,
                                                  const float* __restrict__ wp,
                                                  const float* __restrict__ wo) {
    const int stride = CVT_GRID * 256;
    for (int base = blockIdx.x * 256 + threadIdx.x; base < CVT_TOT; base += 4 * stride) {
        float4 v[4];
        int    idxs[4];
        int    nv = 0;
#pragma unroll
        for (int u = 0; u < 4; u++) {
            int idx = base + u * stride;
            if (idx < CVT_TOT) {
                const float* src;
                int i;
                if (idx < NX4)             { src = x;  i = idx; }
                else if (idx < NX4 + NWP4) { src = wp; i = idx - NX4; }
                else                       { src = wo; i = idx - NX4 - NWP4; }
                v[nv] = *(const float4*)&src[(size_t)i * 4];
                idxs[nv] = idx;
                nv++;
            }
        }
#pragma unroll
        for (int u = 0; u < 4; u++) {
            if (u < nv) {
                int idx = idxs[u];
                __nv_bfloat16* dst;
                int i;
                if (idx < NX4)             { dst = g_xh;  i = idx; }
                else if (idx < NX4 + NWP4) { dst = g_wph; i = idx - NX4; }
                else                       { dst = g_woh; i = idx - NX4 - NWP4; }
                *(__nv_bfloat162*)&dst[(size_t)i * 4]     = __floats2bfloat162_rn(v[u].x, v[u].y);
                *(__nv_bfloat162*)&dst[(size_t)i * 4 + 2] = __floats2bfloat162_rn(v[u].z, v[u].w);
            }
        }
    }
}

// ---------------------------------------------------------------------------
// Kernel 1: QKV projection. CTA 128x128, 8 warps, k-chunks 64, 3-stage ring.
// (identical to the 115.2us round-13 build)
// ---------------------------------------------------------------------------
#define Q_ST 17408u
#define Q_SM (6u * Q_ST)
__global__ void __launch_bounds__(256, 2) qkv3(const float* __restrict__ bp) {
    extern __shared__ __align__(16) char dsm[];
    const unsigned sa = smem_u32(dsm), sbb = sa + 3 * Q_ST;
    const int b  = blockIdx.z;
    const int m0 = blockIdx.y * 128;
    const int n0 = blockIdx.x * 128;
    const int tid = threadIdx.x, warp = tid >> 5, lane = tid & 31;
    const int g = lane >> 2, t = lane & 3;
    const int l7 = lane & 7, lq1 = (lane >> 3) & 1, lq2 = (lane >> 4) & 1;
    const int wm = (warp >> 1) * 32, wn = (warp & 1) * 64;
    const __nv_bfloat16* xb = g_xh + (size_t)b * C_ * S_;

    const int lk = tid >> 4, lc = (tid & 15) * 8;

#pragma unroll
    for (int p = 0; p < 4; p++) {
        int kk = lk + p * 16;
        CP16(sa  + (kk * 136 + lc) * 2, xb + (size_t)kk * S_ + m0 + lc);
        CP16(sbb + (kk * 136 + lc) * 2, g_wph + (size_t)kk * O3_ + n0 + lc);
    }
    CPCOMMIT();

    float acc[2][8][4];
#pragma unroll
    for (int mt = 0; mt < 2; mt++)
#pragma unroll
        for (int nt = 0; nt < 8; nt++)
#pragma unroll
            for (int i = 0; i < 4; i++) acc[mt][nt][i] = 0.f;

#pragma unroll
    for (int it = 0; it < 4; it++) {
        if (it + 1 < 4) {
            const int k0 = (it + 1) * 64;
            const unsigned ao = sa  + ((it + 1) % 3) * Q_ST;
            const unsigned bo = sbb + ((it + 1) % 3) * Q_ST;
#pragma unroll
            for (int p = 0; p < 4; p++) {
                int kk = lk + p * 16;
                CP16(ao + (kk * 136 + lc) * 2, xb + (size_t)(k0 + kk) * S_ + m0 + lc);
                CP16(bo + (kk * 136 + lc) * 2, g_wph + (size_t)(k0 + kk) * O3_ + n0 + lc);
            }
            CPCOMMIT();
            CPWAIT(1);
        } else {
            CPWAIT(0);
        }
        __syncthreads();
        const unsigned ao = sa  + (it % 3) * Q_ST;
        const unsigned bo = sbb + (it % 3) * Q_ST;
#pragma unroll
        for (int ks = 0; ks < 4; ks++) {
            const int kb = ks * 16;
            unsigned a[2][4];
#pragma unroll
            for (int mt = 0; mt < 2; mt++)
                ldsm4t(a[mt][0], a[mt][1], a[mt][2], a[mt][3],
                       ao + ((kb + lq2 * 8 + l7) * 136 + wm + mt * 16 + lq1 * 8) * 2);
#pragma unroll
            for (int np = 0; np < 4; np++) {
                unsigned r0, r1, r2, r3;
                ldsm4t(r0, r1, r2, r3,
                       bo + ((kb + lq1 * 8 + l7) * 136 + wn + np * 16 + lq2 * 8) * 2);
                unsigned blo[2] = {r0, r1}, bhi[2] = {r2, r3};
#pragma unroll
                for (int mt = 0; mt < 2; mt++) {
                    mma16(acc[mt][2 * np],     a[mt], blo);
                    mma16(acc[mt][2 * np + 1], a[mt], bhi);
                }
            }
        }
    }

    __syncthreads();
    __nv_bfloat16* Ts = (__nv_bfloat16*)dsm;
#pragma unroll
    for (int mt = 0; mt < 2; mt++) {
        const int r1 = wm + mt * 16 + g, r2 = r1 + 8;
#pragma unroll
        for (int nt = 0; nt < 8; nt++) {
            const int cn = wn + nt * 8 + 2 * t;
            float2 bb = *(const float2*)&bp[n0 + cn];
            *(unsigned*)&Ts[r1 * 136 + cn] = packbf(acc[mt][nt][0] + bb.x, acc[mt][nt][1] + bb.y);
            *(unsigned*)&Ts[r2 * 136 + cn] = packbf(acc[mt][nt][2] + bb.x, acc[mt][nt][3] + bb.y);
        }
    }
    __syncthreads();
    __nv_bfloat16* qb = g_qkvh + (size_t)b * S_ * O3_;
#pragma unroll
    for (int i = 0; i < 8; i++) {
        int idx = tid + i * 256;
        int row = idx >> 4, c16 = (idx & 15) * 8;
        uint4 v = *(uint4*)&Ts[row * 136 + c16];
        *(uint4*)&qb[(size_t)(m0 + row) * O3_ + n0 + c16] = v;
    }
}

// ---------------------------------------------------------------------------
// Kernel 2: flash attention. 256 threads, 8 warps x 32 q-rows (i-tile 256),
// K/V fragment reuse across 2 m-subtiles, 3-stage ring, no-max softmax.
// (identical to the 115.2us round-13 build)
// ---------------------------------------------------------------------------
#define KVS 9216u
__global__ void __launch_bounds__(256, 1) attn_kernel() {
    __shared__ __align__(16) __nv_bfloat16 sm[6 * 64 * 72];   // K[3] then V[3]
    const int i0 = blockIdx.x * 256;
    const int h  = blockIdx.y;
    const int b  = blockIdx.z;
    const __nv_bfloat16* qkv = g_qkvh + (size_t)b * S_ * O3_;

    const int tid = threadIdx.x, warp = tid >> 5, lane = tid & 31;
    const int g = lane >> 2, t = lane & 3;
    const int l7 = lane & 7, lq1 = (lane >> 3) & 1, lq2 = (lane >> 4) & 1;
    const unsigned ks_b = smem_u32(sm), vs_b = ks_b + 3 * KVS;
    const float k2 = SCALE_ * LOG2E_;

    const int lj = tid >> 2, lc8 = (tid & 3) * 16;

    unsigned qa[2][4][4];
#pragma unroll
    for (int mt = 0; mt < 2; mt++) {
        const __nv_bfloat16* q1 = qkv + (size_t)(i0 + warp * 32 + mt * 16 + g) * O3_ + h * 192;
        const __nv_bfloat16* q2 = q1 + 8 * O3_;
#pragma unroll
        for (int c = 0; c < 4; c++) {
            qa[mt][c][0] = *(const unsigned*)&q1[c * 16 + 2 * t];
            qa[mt][c][1] = *(const unsigned*)&q2[c * 16 + 2 * t];
            qa[mt][c][2] = *(const unsigned*)&q1[c * 16 + 8 + 2 * t];
            qa[mt][c][3] = *(const unsigned*)&q2[c * 16 + 8 + 2 * t];
        }
    }

    float oacc[2][8][4];
#pragma unroll
    for (int mt = 0; mt < 2; mt++)
#pragma unroll
        for (int nt = 0; nt < 8; nt++)
#pragma unroll
            for (int i = 0; i < 4; i++) oacc[mt][nt][i] = 0.f;
    float lsum[2][2] = {{0.f, 0.f}, {0.f, 0.f}};

    {   // tile 0 -> stage 0
        const __nv_bfloat16* src = qkv + (size_t)lj * O3_ + h * 192 + 64 + lc8;
        CP16(ks_b + (lj * 72 + lc8) * 2,     src);
        CP16(ks_b + (lj * 72 + lc8 + 8) * 2, src + 8);
        CP16(vs_b + (lj * 72 + lc8) * 2,     src + 64);
        CP16(vs_b + (lj * 72 + lc8 + 8) * 2, src + 72);
        CPCOMMIT();
    }

    for (int jt = 0; jt < 16; jt++) {
        if (jt + 1 < 16) {
            const unsigned ko = ks_b + ((jt + 1) % 3) * KVS;
            const unsigned vo = vs_b + ((jt + 1) % 3) * KVS;
            const __nv_bfloat16* src = qkv + (size_t)((jt + 1) * 64 + lj) * O3_ + h * 192 + 64 + lc8;
            CP16(ko + (lj * 72 + lc8) * 2,     src);
            CP16(ko + (lj * 72 + lc8 + 8) * 2, src + 8);
            CP16(vo + (lj * 72 + lc8) * 2,     src + 64);
            CP16(vo + (lj * 72 + lc8 + 8) * 2, src + 72);
            CPCOMMIT();
            CPWAIT(1);
        } else {
            CPWAIT(0);
        }
        __syncthreads();
        const unsigned ko = ks_b + (jt % 3) * KVS;
        const unsigned vo = vs_b + (jt % 3) * KVS;

        float sacc[2][8][4];
#pragma unroll
        for (int mt = 0; mt < 2; mt++)
#pragma unroll
            for (int nt = 0; nt < 8; nt++)
#pragma unroll
                for (int i = 0; i < 4; i++) sacc[mt][nt][i] = 0.f;
#pragma unroll
        for (int c = 0; c < 4; c++) {
            const int kb = c * 16;
#pragma unroll
            for (int np = 0; np < 4; np++) {
                unsigned r0, r1, r2, r3;
                ldsm4(r0, r1, r2, r3,
                      ko + ((np * 16 + lq2 * 8 + l7) * 72 + kb + lq1 * 8) * 2);
                unsigned blo[2] = {r0, r1}, bhi[2] = {r2, r3};
#pragma unroll
                for (int mt = 0; mt < 2; mt++) {
                    mma16(sacc[mt][2 * np],     qa[mt][c], blo);
                    mma16(sacc[mt][2 * np + 1], qa[mt][c], bhi);
                }
            }
        }

        unsigned pa[2][4][4];
#pragma unroll
        for (int mt = 0; mt < 2; mt++) {
#pragma unroll
            for (int jc = 0; jc < 4; jc++) {
                float p0 = exp2fast(sacc[mt][2 * jc][0] * k2);
                float p1 = exp2fast(sacc[mt][2 * jc][1] * k2);
                float p2 = exp2fast(sacc[mt][2 * jc][2] * k2);
                float p3 = exp2fast(sacc[mt][2 * jc][3] * k2);
                float p4 = exp2fast(sacc[mt][2 * jc + 1][0] * k2);
                float p5 = exp2fast(sacc[mt][2 * jc + 1][1] * k2);
                float p6 = exp2fast(sacc[mt][2 * jc + 1][2] * k2);
                float p7 = exp2fast(sacc[mt][2 * jc + 1][3] * k2);
                lsum[mt][0] += (p0 + p1) + (p4 + p5);
                lsum[mt][1] += (p2 + p3) + (p6 + p7);
                pa[mt][jc][0] = packbf(p0, p1);
                pa[mt][jc][1] = packbf(p2, p3);
                pa[mt][jc][2] = packbf(p4, p5);
                pa[mt][jc][3] = packbf(p6, p7);
            }
        }

#pragma unroll
        for (int jc = 0; jc < 4; jc++) {
            const int kc = jc * 16;
#pragma unroll
            for (int dp = 0; dp < 4; dp++) {
                unsigned r0, r1, r2, r3;
                ldsm4t(r0, r1, r2, r3,
                       vo + ((kc + lq1 * 8 + l7) * 72 + dp * 16 + lq2 * 8) * 2);
                unsigned blo[2] = {r0, r1}, bhi[2] = {r2, r3};
#pragma unroll
                for (int mt = 0; mt < 2; mt++) {
                    mma16(oacc[mt][2 * dp],     pa[mt][jc], blo);
                    mma16(oacc[mt][2 * dp + 1], pa[mt][jc], bhi);
                }
            }
        }
    }

#pragma unroll
    for (int mt = 0; mt < 2; mt++) {
        float l1 = lsum[mt][0], l2 = lsum[mt][1];
        l1 += __shfl_xor_sync(0xffffffffu, l1, 1);
        l1 += __shfl_xor_sync(0xffffffffu, l1, 2);
        l2 += __shfl_xor_sync(0xffffffffu, l2, 1);
        l2 += __shfl_xor_sync(0xffffffffu, l2, 2);
        const float inv1 = 1.f / l1, inv2 = 1.f / l2;
        __nv_bfloat16* ob1 = g_aoh + (size_t)b * S_ * C_
                           + (size_t)(i0 + warp * 32 + mt * 16 + g) * C_ + h * 64;
        __nv_bfloat16* ob2 = ob1 + 8 * C_;
#pragma unroll
        for (int nt = 0; nt < 8; nt++) {
            *(__nv_bfloat162*)&ob1[nt * 8 + 2 * t] =
                __floats2bfloat162_rn(oacc[mt][nt][0] * inv1, oacc[mt][nt][1] * inv1);
            *(__nv_bfloat162*)&ob2[nt * 8 + 2 * t] =
                __floats2bfloat162_rn(oacc[mt][nt][2] * inv2, oacc[mt][nt][3] * inv2);
        }
    }
}

// ---------------------------------------------------------------------------
// Kernel 3: out projection. CTA 256m x 128n, 512 threads, 16 warps,
// warp tile 64x32, k-chunks 64, 3-stage ring. (identical to R12/R13)
// ---------------------------------------------------------------------------
#define O_AST 36864u
#define O_BST 17408u
#define O_SM  (3u * (O_AST + O_BST))
#define O_EPIW 260
__global__ void __launch_bounds__(512, 1) out3(const float* __restrict__ bo,
                                               const float* __restrict__ x,
                                               float* __restrict__ out) {
    extern __shared__ __align__(16) char dsm[];
    const unsigned sa = smem_u32(dsm), sbb = sa + 3 * O_AST;
    const int b  = blockIdx.z;
    const int m0 = blockIdx.y * 256;
    const int n0 = blockIdx.x * 128;
    const int tid = threadIdx.x, warp = tid >> 5, lane = tid & 31;
    const int g = lane >> 2, t = lane & 3;
    const int l7 = lane & 7, lq1 = (lane >> 3) & 1, lq2 = (lane >> 4) & 1;
    const int wm = (warp >> 2) * 64, wn = (warp & 3) * 32;
    const __nv_bfloat16* ab = g_aoh + (size_t)b * S_ * C_;

    const int am = tid >> 1, ak = (tid & 1) * 8;
    const int bk = tid >> 4, bc = (tid & 15) * 8;

#pragma unroll
    for (int p = 0; p < 4; p++)
        CP16(sa + (am * 72 + ak + p * 16) * 2, ab + (size_t)(m0 + am) * C_ + ak + p * 16);
#pragma unroll
    for (int p = 0; p < 2; p++) {
        int kk = bk + p * 32;
        CP16(sbb + (kk * 136 + bc) * 2, g_woh + (size_t)kk * C_ + n0 + bc);
    }
    CPCOMMIT();

    float acc[4][4][4];
#pragma unroll
    for (int am2 = 0; am2 < 4; am2++)
#pragma unroll
        for (int nt = 0; nt < 4; nt++)
#pragma unroll
            for (int i = 0; i < 4; i++) acc[am2][nt][i] = 0.f;

#pragma unroll
    for (int it = 0; it < 4; it++) {
        if (it + 1 < 4) {
            const int k0 = (it + 1) * 64;
            const unsigned ao = sa  + ((it + 1) % 3) * O_AST;
            const unsigned bo2 = sbb + ((it + 1) % 3) * O_BST;
#pragma unroll
            for (int p = 0; p < 4; p++)
                CP16(ao + (am * 72 + ak + p * 16) * 2,
                     ab + (size_t)(m0 + am) * C_ + k0 + ak + p * 16);
#pragma unroll
            for (int p = 0; p < 2; p++) {
                int kk = bk + p * 32;
                CP16(bo2 + (kk * 136 + bc) * 2, g_woh + (size_t)(k0 + kk) * C_ + n0 + bc);
            }
            CPCOMMIT();
            CPWAIT(1);
        } else {
            CPWAIT(0);
        }
        __syncthreads();
        const unsigned ao = sa  + (it % 3) * O_AST;
        const unsigned bo2 = sbb + (it % 3) * O_BST;
#pragma unroll
        for (int ks = 0; ks < 4; ks++) {
            const int kb = ks * 16;
            unsigned a[4][4];
#pragma unroll
            for (int am2 = 0; am2 < 4; am2++)
                ldsm4(a[am2][0], a[am2][1], a[am2][2], a[am2][3],
                      ao + ((wm + am2 * 16 + lq1 * 8 + l7) * 72 + kb + lq2 * 8) * 2);
#pragma unroll
            for (int np = 0; np < 2; np++) {
                unsigned r0, r1, r2, r3;
                ldsm4t(r0, r1, r2, r3,
                       bo2 + ((kb + lq1 * 8 + l7) * 136 + wn + np * 16 + lq2 * 8) * 2);
                unsigned blo[2] = {r0, r1}, bhi[2] = {r2, r3};
#pragma unroll
                for (int am2 = 0; am2 < 4; am2++) {
                    mma16(acc[am2][2 * np],     a[am2], blo);
                    mma16(acc[am2][2 * np + 1], a[am2], bhi);
                }
            }
        }
    }

    __syncthreads();
    float* Os = (float*)dsm;
#pragma unroll
    for (int am2 = 0; am2 < 4; am2++) {
        const int r1 = wm + am2 * 16 + g, r2 = r1 + 8;
#pragma unroll
        for (int nt = 0; nt < 4; nt++) {
            const int cn = wn + nt * 8 + 2 * t;
            Os[cn * O_EPIW + r1]       = acc[am2][nt][0];
            Os[(cn + 1) * O_EPIW + r1] = acc[am2][nt][1];
            Os[cn * O_EPIW + r2]       = acc[am2][nt][2];
            Os[(cn + 1) * O_EPIW + r2] = acc[am2][nt][3];
        }
    }
    __syncthreads();
    const float* xb = x + (size_t)b * C_ * S_;
    float* ob = out + (size_t)b * C_ * S_;
#pragma unroll
    for (int i = 0; i < 16; i++) {
        int idx = tid + i * 512;
        int row = idx >> 6, c4 = (idx & 63) * 4;
        const int ch = n0 + row;
        const float bias = bo[ch];
        float4 v = *(float4*)&Os[row * O_EPIW + c4];
        float4 xr = *(const float4*)&xb[(size_t)ch * S_ + m0 + c4];
        v.x += bias + xr.x; v.y += bias + xr.y;
        v.z += bias + xr.z; v.w += bias + xr.w;
        *(float4*)&ob[(size_t)ch * S_ + m0 + c4] = v;
    }
}

// ---------------------------------------------------------------------------
extern "C" void kernel_launch(void* const* d_in, const int* in_sizes, int n_in,
                              void* d_out, int out_size) {
    const float* x  = (const float*)d_in[0];
    const float* wp = (const float*)d_in[1];
    const float* bp = (const float*)d_in[2];
    const float* wo = (const float*)d_in[3];
    const float* bo = (const float*)d_in[4];
    float* out = (float*)d_out;

    static int attr_set = 0;
    if (!attr_set) {
        cudaFuncSetAttribute(qkv3, cudaFuncAttributeMaxDynamicSharedMemorySize, (int)Q_SM);
        cudaFuncSetAttribute(out3, cudaFuncAttributeMaxDynamicSharedMemorySize, (int)O_SM);
        attr_set = 1;
    }

    cvt_inputs<<<CVT_GRID, 256>>>(x, wp, wo);
    qkv3<<<dim3(O3_ / 128, S_ / 128, B_), 256, Q_SM>>>(bp);
    attn_kernel<<<dim3(S_ / 256, H_, B_), 256>>>();
    out3<<<dim3(C_ / 128, S_ / 256, B_), 512, O_SM>>>(bo, x, out);
}

// round 17
// speedup vs baseline: 1.2329x; 1.1513x over previous
#include <cuda_runtime.h>
#include <cuda_bf16.h>

#define B_   16
#define C_   256
#define S_   1024
#define H_   4
#define O3_  768
#define SCALE_ 0.125f
#define LOG2E_ 1.4426950408889634f

__device__ __align__(16) __nv_bfloat16 g_qkvh[B_ * S_ * O3_];  // [b][s][768]
__device__ __align__(16) __nv_bfloat16 g_aoh [B_ * S_ * C_];   // [b][s][256]
__device__ __align__(16) __nv_bfloat16 g_xh  [B_ * C_ * S_];   // [b][c][s]
__device__ __align__(16) __nv_bfloat16 g_wph [C_ * O3_];
__device__ __align__(16) __nv_bfloat16 g_woh [C_ * C_];

// ---------------------------------------------------------------------------
__device__ __forceinline__ unsigned smem_u32(const void* p) {
    return (unsigned)__cvta_generic_to_shared(p);
}
__device__ __forceinline__ void ldsm4(unsigned& r0, unsigned& r1, unsigned& r2, unsigned& r3,
                                      unsigned a) {
    asm volatile("ldmatrix.sync.aligned.m8n8.x4.shared.b16 {%0,%1,%2,%3},[%4];"
                 : "=r"(r0), "=r"(r1), "=r"(r2), "=r"(r3) : "r"(a));
}
__device__ __forceinline__ void ldsm4t(unsigned& r0, unsigned& r1, unsigned& r2, unsigned& r3,
                                       unsigned a) {
    asm volatile("ldmatrix.sync.aligned.m8n8.x4.trans.shared.b16 {%0,%1,%2,%3},[%4];"
                 : "=r"(r0), "=r"(r1), "=r"(r2), "=r"(r3) : "r"(a));
}
__device__ __forceinline__ void mma16(float c[4], const unsigned a[4], const unsigned b[2]) {
    asm volatile("mma.sync.aligned.m16n8k16.row.col.f32.bf16.bf16.f32 "
                 "{%0,%1,%2,%3},{%4,%5,%6,%7},{%8,%9},{%0,%1,%2,%3};"
                 : "+f"(c[0]), "+f"(c[1]), "+f"(c[2]), "+f"(c[3])
                 : "r"(a[0]), "r"(a[1]), "r"(a[2]), "r"(a[3]),
                   "r"(b[0]), "r"(b[1]));
}
#define CP16(dst, src) \
    asm volatile("cp.async.cg.shared.global [%0], [%1], 16;" :: "r"(dst), "l"(src))
#define CPCOMMIT() asm volatile("cp.async.commit_group;")
#define CPWAIT(n)  asm volatile("cp.async.wait_group %0;" :: "n"(n))

__device__ __forceinline__ unsigned packbf(float lo, float hi) {
    __nv_bfloat162 v = __floats2bfloat162_rn(lo, hi);
    return *(unsigned*)&v;
}
// single-instruction MUFU exponential (base 2)
__device__ __forceinline__ float ex2a(float x) {
    float y;
    asm("ex2.approx.ftz.f32 %0, %1;" : "=f"(y) : "f"(x));
    return y;
}
// FMA-pipe exp2 (kept for non-hot paths if needed)
__device__ __forceinline__ float exp2fast(float x) {
    x = fmaxf(x, -126.0f);
    float z = x + 12582912.0f;
    int   n = __float_as_int(z) - 0x4B400000;
    float f = x - (z - 12582912.0f);
    float p = 0.0013333558f;
    p = fmaf(p, f, 0.0096181291f);
    p = fmaf(p, f, 0.0555041087f);
    p = fmaf(p, f, 0.2402265070f);
    p = fmaf(p, f, 0.6931471806f);
    p = fmaf(p, f, 1.0f);
    return __int_as_float(__float_as_int(p) + (n << 23));
}

// ---------------------------------------------------------------------------
// Kernel 0: convert inputs to bf16 (high-MLP grid-stride).
// ---------------------------------------------------------------------------
#define NX4  (B_ * C_ * S_ / 4)
#define NWP4 (C_ * O3_ / 4)
#define NWO4 (C_ * C_ / 4)
#define CVT_TOT   (NX4 + NWP4 + NWO4)
#define CVT_GRID  1184
__global__ void __launch_bounds__(256) cvt_inputs(const float* __restrict__ x,
                                                  const float* __restrict__ wp,
                                                  const float* __restrict__ wo) {
    const int stride = CVT_GRID * 256;
    for (int base = blockIdx.x * 256 + threadIdx.x; base < CVT_TOT; base += 4 * stride) {
        float4 v[4];
        int    idxs[4];
        int    nv = 0;
#pragma unroll
        for (int u = 0; u < 4; u++) {
            int idx = base + u * stride;
            if (idx < CVT_TOT) {
                const float* src;
                int i;
                if (idx < NX4)             { src = x;  i = idx; }
                else if (idx < NX4 + NWP4) { src = wp; i = idx - NX4; }
                else                       { src = wo; i = idx - NX4 - NWP4; }
                v[nv] = *(const float4*)&src[(size_t)i * 4];
                idxs[nv] = idx;
                nv++;
            }
        }
#pragma unroll
        for (int u = 0; u < 4; u++) {
            if (u < nv) {
                int idx = idxs[u];
                __nv_bfloat16* dst;
                int i;
                if (idx < NX4)             { dst = g_xh;  i = idx; }
                else if (idx < NX4 + NWP4) { dst = g_wph; i = idx - NX4; }
                else                       { dst = g_woh; i = idx - NX4 - NWP4; }
                *(__nv_bfloat162*)&dst[(size_t)i * 4]     = __floats2bfloat162_rn(v[u].x, v[u].y);
                *(__nv_bfloat162*)&dst[(size_t)i * 4 + 2] = __floats2bfloat162_rn(v[u].z, v[u].w);
            }
        }
    }
}

// ---------------------------------------------------------------------------
// Kernel 1: QKV projection. CTA 128x128, 8 warps, k-chunks 64, 3-stage ring.
// ---------------------------------------------------------------------------
#define Q_ST 17408u
#define Q_SM (6u * Q_ST)
__global__ void __launch_bounds__(256, 2) qkv3(const float* __restrict__ bp) {
    extern __shared__ __align__(16) char dsm[];
    const unsigned sa = smem_u32(dsm), sbb = sa + 3 * Q_ST;
    const int b  = blockIdx.z;
    const int m0 = blockIdx.y * 128;
    const int n0 = blockIdx.x * 128;
    const int tid = threadIdx.x, warp = tid >> 5, lane = tid & 31;
    const int g = lane >> 2, t = lane & 3;
    const int l7 = lane & 7, lq1 = (lane >> 3) & 1, lq2 = (lane >> 4) & 1;
    const int wm = (warp >> 1) * 32, wn = (warp & 1) * 64;
    const __nv_bfloat16* xb = g_xh + (size_t)b * C_ * S_;

    const int lk = tid >> 4, lc = (tid & 15) * 8;

#pragma unroll
    for (int p = 0; p < 4; p++) {
        int kk = lk + p * 16;
        CP16(sa  + (kk * 136 + lc) * 2, xb + (size_t)kk * S_ + m0 + lc);
        CP16(sbb + (kk * 136 + lc) * 2, g_wph + (size_t)kk * O3_ + n0 + lc);
    }
    CPCOMMIT();

    float acc[2][8][4];
#pragma unroll
    for (int mt = 0; mt < 2; mt++)
#pragma unroll
        for (int nt = 0; nt < 8; nt++)
#pragma unroll
            for (int i = 0; i < 4; i++) acc[mt][nt][i] = 0.f;

#pragma unroll
    for (int it = 0; it < 4; it++) {
        if (it + 1 < 4) {
            const int k0 = (it + 1) * 64;
            const unsigned ao = sa  + ((it + 1) % 3) * Q_ST;
            const unsigned bo = sbb + ((it + 1) % 3) * Q_ST;
#pragma unroll
            for (int p = 0; p < 4; p++) {
                int kk = lk + p * 16;
                CP16(ao + (kk * 136 + lc) * 2, xb + (size_t)(k0 + kk) * S_ + m0 + lc);
                CP16(bo + (kk * 136 + lc) * 2, g_wph + (size_t)(k0 + kk) * O3_ + n0 + lc);
            }
            CPCOMMIT();
            CPWAIT(1);
        } else {
            CPWAIT(0);
        }
        __syncthreads();
        const unsigned ao = sa  + (it % 3) * Q_ST;
        const unsigned bo = sbb + (it % 3) * Q_ST;
#pragma unroll
        for (int ks = 0; ks < 4; ks++) {
            const int kb = ks * 16;
            unsigned a[2][4];
#pragma unroll
            for (int mt = 0; mt < 2; mt++)
                ldsm4t(a[mt][0], a[mt][1], a[mt][2], a[mt][3],
                       ao + ((kb + lq2 * 8 + l7) * 136 + wm + mt * 16 + lq1 * 8) * 2);
#pragma unroll
            for (int np = 0; np < 4; np++) {
                unsigned r0, r1, r2, r3;
                ldsm4t(r0, r1, r2, r3,
                       bo + ((kb + lq1 * 8 + l7) * 136 + wn + np * 16 + lq2 * 8) * 2);
                unsigned blo[2] = {r0, r1}, bhi[2] = {r2, r3};
#pragma unroll
                for (int mt = 0; mt < 2; mt++) {
                    mma16(acc[mt][2 * np],     a[mt], blo);
                    mma16(acc[mt][2 * np + 1], a[mt], bhi);
                }
            }
        }
    }

    __syncthreads();
    __nv_bfloat16* Ts = (__nv_bfloat16*)dsm;
#pragma unroll
    for (int mt = 0; mt < 2; mt++) {
        const int r1 = wm + mt * 16 + g, r2 = r1 + 8;
#pragma unroll
        for (int nt = 0; nt < 8; nt++) {
            const int cn = wn + nt * 8 + 2 * t;
            float2 bb = *(const float2*)&bp[n0 + cn];
            *(unsigned*)&Ts[r1 * 136 + cn] = packbf(acc[mt][nt][0] + bb.x, acc[mt][nt][1] + bb.y);
            *(unsigned*)&Ts[r2 * 136 + cn] = packbf(acc[mt][nt][2] + bb.x, acc[mt][nt][3] + bb.y);
        }
    }
    __syncthreads();
    __nv_bfloat16* qb = g_qkvh + (size_t)b * S_ * O3_;
#pragma unroll
    for (int i = 0; i < 8; i++) {
        int idx = tid + i * 256;
        int row = idx >> 4, c16 = (idx & 15) * 8;
        uint4 v = *(uint4*)&Ts[row * 136 + c16];
        *(uint4*)&qb[(size_t)(m0 + row) * O3_ + n0 + c16] = v;
    }
}

// ---------------------------------------------------------------------------
// Kernel 2: flash attention. 256 threads, 8 warps x 32 q-rows (i-tile 256),
// K/V fragment reuse, 3-stage ring, no-max softmax with MUFU ex2.approx.
// ---------------------------------------------------------------------------
#define KVS 9216u
__global__ void __launch_bounds__(256, 1) attn_kernel() {
    __shared__ __align__(16) __nv_bfloat16 sm[6 * 64 * 72];   // K[3] then V[3]
    const int i0 = blockIdx.x * 256;
    const int h  = blockIdx.y;
    const int b  = blockIdx.z;
    const __nv_bfloat16* qkv = g_qkvh + (size_t)b * S_ * O3_;

    const int tid = threadIdx.x, warp = tid >> 5, lane = tid & 31;
    const int g = lane >> 2, t = lane & 3;
    const int l7 = lane & 7, lq1 = (lane >> 3) & 1, lq2 = (lane >> 4) & 1;
    const unsigned ks_b = smem_u32(sm), vs_b = ks_b + 3 * KVS;
    const float k2 = SCALE_ * LOG2E_;

    const int lj = tid >> 2, lc8 = (tid & 3) * 16;

    unsigned qa[2][4][4];
#pragma unroll
    for (int mt = 0; mt < 2; mt++) {
        const __nv_bfloat16* q1 = qkv + (size_t)(i0 + warp * 32 + mt * 16 + g) * O3_ + h * 192;
        const __nv_bfloat16* q2 = q1 + 8 * O3_;
#pragma unroll
        for (int c = 0; c < 4; c++) {
            qa[mt][c][0] = *(const unsigned*)&q1[c * 16 + 2 * t];
            qa[mt][c][1] = *(const unsigned*)&q2[c * 16 + 2 * t];
            qa[mt][c][2] = *(const unsigned*)&q1[c * 16 + 8 + 2 * t];
            qa[mt][c][3] = *(const unsigned*)&q2[c * 16 + 8 + 2 * t];
        }
    }

    float oacc[2][8][4];
#pragma unroll
    for (int mt = 0; mt < 2; mt++)
#pragma unroll
        for (int nt = 0; nt < 8; nt++)
#pragma unroll
            for (int i = 0; i < 4; i++) oacc[mt][nt][i] = 0.f;
    float lsum[2][2] = {{0.f, 0.f}, {0.f, 0.f}};

    {   // tile 0 -> stage 0
        const __nv_bfloat16* src = qkv + (size_t)lj * O3_ + h * 192 + 64 + lc8;
        CP16(ks_b + (lj * 72 + lc8) * 2,     src);
        CP16(ks_b + (lj * 72 + lc8 + 8) * 2, src + 8);
        CP16(vs_b + (lj * 72 + lc8) * 2,     src + 64);
        CP16(vs_b + (lj * 72 + lc8 + 8) * 2, src + 72);
        CPCOMMIT();
    }

    for (int jt = 0; jt < 16; jt++) {
        if (jt + 1 < 16) {
            const unsigned ko = ks_b + ((jt + 1) % 3) * KVS;
            const unsigned vo = vs_b + ((jt + 1) % 3) * KVS;
            const __nv_bfloat16* src = qkv + (size_t)((jt + 1) * 64 + lj) * O3_ + h * 192 + 64 + lc8;
            CP16(ko + (lj * 72 + lc8) * 2,     src);
            CP16(ko + (lj * 72 + lc8 + 8) * 2, src + 8);
            CP16(vo + (lj * 72 + lc8) * 2,     src + 64);
            CP16(vo + (lj * 72 + lc8 + 8) * 2, src + 72);
            CPCOMMIT();
            CPWAIT(1);
        } else {
            CPWAIT(0);
        }
        __syncthreads();
        const unsigned ko = ks_b + (jt % 3) * KVS;
        const unsigned vo = vs_b + (jt % 3) * KVS;

        float sacc[2][8][4];
#pragma unroll
        for (int mt = 0; mt < 2; mt++)
#pragma unroll
            for (int nt = 0; nt < 8; nt++)
#pragma unroll
                for (int i = 0; i < 4; i++) sacc[mt][nt][i] = 0.f;
#pragma unroll
        for (int c = 0; c < 4; c++) {
            const int kb = c * 16;
#pragma unroll
            for (int np = 0; np < 4; np++) {
                unsigned r0, r1, r2, r3;
                ldsm4(r0, r1, r2, r3,
                      ko + ((np * 16 + lq2 * 8 + l7) * 72 + kb + lq1 * 8) * 2);
                unsigned blo[2] = {r0, r1}, bhi[2] = {r2, r3};
#pragma unroll
                for (int mt = 0; mt < 2; mt++) {
                    mma16(sacc[mt][2 * np],     qa[mt][c], blo);
                    mma16(sacc[mt][2 * np + 1], qa[mt][c], bhi);
                }
            }
        }

        // no-max softmax with MUFU ex2 (1 instruction per value)
        unsigned pa[2][4][4];
#pragma unroll
        for (int mt = 0; mt < 2; mt++) {
#pragma unroll
            for (int jc = 0; jc < 4; jc++) {
                float p0 = ex2a(sacc[mt][2 * jc][0] * k2);
                float p1 = ex2a(sacc[mt][2 * jc][1] * k2);
                float p2 = ex2a(sacc[mt][2 * jc][2] * k2);
                float p3 = ex2a(sacc[mt][2 * jc][3] * k2);
                float p4 = ex2a(sacc[mt][2 * jc + 1][0] * k2);
                float p5 = ex2a(sacc[mt][2 * jc + 1][1] * k2);
                float p6 = ex2a(sacc[mt][2 * jc + 1][2] * k2);
                float p7 = ex2a(sacc[mt][2 * jc + 1][3] * k2);
                lsum[mt][0] += (p0 + p1) + (p4 + p5);
                lsum[mt][1] += (p2 + p3) + (p6 + p7);
                pa[mt][jc][0] = packbf(p0, p1);
                pa[mt][jc][1] = packbf(p2, p3);
                pa[mt][jc][2] = packbf(p4, p5);
                pa[mt][jc][3] = packbf(p6, p7);
            }
        }

#pragma unroll
        for (int jc = 0; jc < 4; jc++) {
            const int kc = jc * 16;
#pragma unroll
            for (int dp = 0; dp < 4; dp++) {
                unsigned r0, r1, r2, r3;
                ldsm4t(r0, r1, r2, r3,
                       vo + ((kc + lq1 * 8 + l7) * 72 + dp * 16 + lq2 * 8) * 2);
                unsigned blo[2] = {r0, r1}, bhi[2] = {r2, r3};
#pragma unroll
                for (int mt = 0; mt < 2; mt++) {
                    mma16(oacc[mt][2 * dp],     pa[mt][jc], blo);
                    mma16(oacc[mt][2 * dp + 1], pa[mt][jc], bhi);
                }
            }
        }
    }

#pragma unroll
    for (int mt = 0; mt < 2; mt++) {
        float l1 = lsum[mt][0], l2 = lsum[mt][1];
        l1 += __shfl_xor_sync(0xffffffffu, l1, 1);
        l1 += __shfl_xor_sync(0xffffffffu, l1, 2);
        l2 += __shfl_xor_sync(0xffffffffu, l2, 1);
        l2 += __shfl_xor_sync(0xffffffffu, l2, 2);
        const float inv1 = 1.f / l1, inv2 = 1.f / l2;
        __nv_bfloat16* ob1 = g_aoh + (size_t)b * S_ * C_
                           + (size_t)(i0 + warp * 32 + mt * 16 + g) * C_ + h * 64;
        __nv_bfloat16* ob2 = ob1 + 8 * C_;
#pragma unroll
        for (int nt = 0; nt < 8; nt++) {
            *(__nv_bfloat162*)&ob1[nt * 8 + 2 * t] =
                __floats2bfloat162_rn(oacc[mt][nt][0] * inv1, oacc[mt][nt][1] * inv1);
            *(__nv_bfloat162*)&ob2[nt * 8 + 2 * t] =
                __floats2bfloat162_rn(oacc[mt][nt][2] * inv2, oacc[mt][nt][3] * inv2);
        }
    }
}

// ---------------------------------------------------------------------------
// Kernel 3: out projection. CTA 256m x 128n, 512 threads, 16 warps,
// warp tile 64x32, k-chunks 64, 3-stage ring.
// ---------------------------------------------------------------------------
#define O_AST 36864u
#define O_BST 17408u
#define O_SM  (3u * (O_AST + O_BST))
#define O_EPIW 260
__global__ void __launch_bounds__(512, 1) out3(const float* __restrict__ bo,
                                               const float* __restrict__ x,
                                               float* __restrict__ out) {
    extern __shared__ __align__(16) char dsm[];
    const unsigned sa = smem_u32(dsm), sbb = sa + 3 * O_AST;
    const int b  = blockIdx.z;
    const int m0 = blockIdx.y * 256;
    const int n0 = blockIdx.x * 128;
    const int tid = threadIdx.x, warp = tid >> 5, lane = tid & 31;
    const int g = lane >> 2, t = lane & 3;
    const int l7 = lane & 7, lq1 = (lane >> 3) & 1, lq2 = (lane >> 4) & 1;
    const int wm = (warp >> 2) * 64, wn = (warp & 3) * 32;
    const __nv_bfloat16* ab = g_aoh + (size_t)b * S_ * C_;

    const int am = tid >> 1, ak = (tid & 1) * 8;
    const int bk = tid >> 4, bc = (tid & 15) * 8;

#pragma unroll
    for (int p = 0; p < 4; p++)
        CP16(sa + (am * 72 + ak + p * 16) * 2, ab + (size_t)(m0 + am) * C_ + ak + p * 16);
#pragma unroll
    for (int p = 0; p < 2; p++) {
        int kk = bk + p * 32;
        CP16(sbb + (kk * 136 + bc) * 2, g_woh + (size_t)kk * C_ + n0 + bc);
    }
    CPCOMMIT();

    float acc[4][4][4];
#pragma unroll
    for (int am2 = 0; am2 < 4; am2++)
#pragma unroll
        for (int nt = 0; nt < 4; nt++)
#pragma unroll
            for (int i = 0; i < 4; i++) acc[am2][nt][i] = 0.f;

#pragma unroll
    for (int it = 0; it < 4; it++) {
        if (it + 1 < 4) {
            const int k0 = (it + 1) * 64;
            const unsigned ao = sa  + ((it + 1) % 3) * O_AST;
            const unsigned bo2 = sbb + ((it + 1) % 3) * O_BST;
#pragma unroll
            for (int p = 0; p < 4; p++)
                CP16(ao + (am * 72 + ak + p * 16) * 2,
                     ab + (size_t)(m0 + am) * C_ + k0 + ak + p * 16);
#pragma unroll
            for (int p = 0; p < 2; p++) {
                int kk = bk + p * 32;
                CP16(bo2 + (kk * 136 + bc) * 2, g_woh + (size_t)(k0 + kk) * C_ + n0 + bc);
            }
            CPCOMMIT();
            CPWAIT(1);
        } else {
            CPWAIT(0);
        }
        __syncthreads();
        const unsigned ao = sa  + (it % 3) * O_AST;
        const unsigned bo2 = sbb + (it % 3) * O_BST;
#pragma unroll
        for (int ks = 0; ks < 4; ks++) {
            const int kb = ks * 16;
            unsigned a[4][4];
#pragma unroll
            for (int am2 = 0; am2 < 4; am2++)
                ldsm4(a[am2][0], a[am2][1], a[am2][2], a[am2][3],
                      ao + ((wm + am2 * 16 + lq1 * 8 + l7) * 72 + kb + lq2 * 8) * 2);
#pragma unroll
            for (int np = 0; np < 2; np++) {
                unsigned r0, r1, r2, r3;
                ldsm4t(r0, r1, r2, r3,
                       bo2 + ((kb + lq1 * 8 + l7) * 136 + wn + np * 16 + lq2 * 8) * 2);
                unsigned blo[2] = {r0, r1}, bhi[2] = {r2, r3};
#pragma unroll
                for (int am2 = 0; am2 < 4; am2++) {
                    mma16(acc[am2][2 * np],     a[am2], blo);
                    mma16(acc[am2][2 * np + 1], a[am2], bhi);
                }
            }
        }
    }

    __syncthreads();
    float* Os = (float*)dsm;
#pragma unroll
    for (int am2 = 0; am2 < 4; am2++) {
        const int r1 = wm + am2 * 16 + g, r2 = r1 + 8;
#pragma unroll
        for (int nt = 0; nt < 4; nt++) {
            const int cn = wn + nt * 8 + 2 * t;
            Os[cn * O_EPIW + r1]       = acc[am2][nt][0];
            Os[(cn + 1) * O_EPIW + r1] = acc[am2][nt][1];
            Os[cn * O_EPIW + r2]       = acc[am2][nt][2];
            Os[(cn + 1) * O_EPIW + r2] = acc[am2][nt][3];
        }
    }
    __syncthreads();
    const float* xb = x + (size_t)b * C_ * S_;
    float* ob = out + (size_t)b * C_ * S_;
#pragma unroll
    for (int i = 0; i < 16; i++) {
        int idx = tid + i * 512;
        int row = idx >> 6, c4 = (idx & 63) * 4;
        const int ch = n0 + row;
        const float bias = bo[ch];
        float4 v = *(float4*)&Os[row * O_EPIW + c4];
        float4 xr = *(const float4*)&xb[(size_t)ch * S_ + m0 + c4];
        v.x += bias + xr.x; v.y += bias + xr.y;
        v.z += bias + xr.z; v.w += bias + xr.w;
        *(float4*)&ob[(size_t)ch * S_ + m0 + c4] = v;
    }
}

// ---------------------------------------------------------------------------
extern "C" void kernel_launch(void* const* d_in, const int* in_sizes, int n_in,
                              void* d_out, int out_size) {
    const float* x  = (const float*)d_in[0];
    const float* wp = (const float*)d_in[1];
    const float* bp = (const float*)d_in[2];
    const float* wo = (const float*)d_in[3];
    const float* bo = (const float*)d_in[4];
    float* out = (float*)d_out;

    static int attr_set = 0;
    if (!attr_set) {
        cudaFuncSetAttribute(qkv3, cudaFuncAttributeMaxDynamicSharedMemorySize, (int)Q_SM);
        cudaFuncSetAttribute(out3, cudaFuncAttributeMaxDynamicSharedMemorySize, (int)O_SM);
        attr_set = 1;
    }

    cvt_inputs<<<CVT_GRID, 256>>>(x, wp, wo);
    qkv3<<<dim3(O3_ / 128, S_ / 128, B_), 256, Q_SM>>>(bp);
    attn_kernel<<<dim3(S_ / 256, H_, B_), 256>>>();
    out3<<<dim3(C_ / 128, S_ / 256, B_), 512, O_SM>>>(bo, x, out);
}